// round 15
// baseline (speedup 1.0000x reference)
#include <cuda_runtime.h>
#include <cuda_bf16.h>
#include <cstdint>
#include <math.h>

#define DD 64
#define KTOT 1024
#define TM 128
#define NTHREADS 256
#define NTILE 64
#define NKT (KTOT / NTILE)
#define THRESH_MAX 5e-4f   // gap threshold in (s - e/2) domain == 1e-3 in dist domain

// ---------------- scratch (no allocations allowed) ----------------
__device__ float          g_enorm[KTOT];
__device__ float          g_eneg2[KTOT];        // -0.5 * ||e||^2 (screen init)
__device__ float          g_ET[KTOT * DD];      // codebook rows, k-major, f32
__device__ __nv_bfloat16  g_Bhi[KTOT * DD];     // bf16 hi split, [code][d]
__device__ __nv_bfloat16  g_Blo[KTOT * DD];     // bf16 lo split, [code][d]
__device__ int            g_hist[KTOT];
__device__ float          g_partial[2048];

// ---------------- PTX helpers (baseline PTX only) ----------------
static __device__ __forceinline__ uint32_t smem_to_u32(const void* p) {
    uint32_t a;
    asm("{ .reg .u64 t; cvta.to.shared.u64 t, %1; cvt.u32.u64 %0, t; }" : "=r"(a) : "l"(p));
    return a;
}
static __device__ __forceinline__ void ldsm4(uint32_t& r0, uint32_t& r1,
    uint32_t& r2, uint32_t& r3, uint32_t addr) {
    asm volatile("ldmatrix.sync.aligned.m8n8.x4.shared.b16 {%0,%1,%2,%3}, [%4];"
        : "=r"(r0), "=r"(r1), "=r"(r2), "=r"(r3) : "r"(addr));
}
static __device__ __forceinline__ void mma_bf16(float* c, const uint32_t* a,
    uint32_t b0, uint32_t b1) {
    asm volatile(
        "mma.sync.aligned.m16n8k16.row.col.f32.bf16.bf16.f32 "
        "{%0,%1,%2,%3}, {%4,%5,%6,%7}, {%8,%9}, {%0,%1,%2,%3};"
        : "+f"(c[0]), "+f"(c[1]), "+f"(c[2]), "+f"(c[3])
        : "r"(a[0]), "r"(a[1]), "r"(a[2]), "r"(a[3]), "r"(b0), "r"(b1));
}
static __device__ __forceinline__ void cpa16(uint32_t dst, const void* src) {
    asm volatile("cp.async.ca.shared.global [%0], [%1], 16;" :: "r"(dst), "l"(src));
}
static __device__ __forceinline__ void cpa4(uint32_t dst, const void* src) {
    asm volatile("cp.async.ca.shared.global [%0], [%1], 4;" :: "r"(dst), "l"(src));
}
static __device__ __forceinline__ void cpa_commit() {
    asm volatile("cp.async.commit_group;" ::: "memory");
}
static __device__ __forceinline__ void cpa_wait0() {
    asm volatile("cp.async.wait_group 0;" ::: "memory");
}
static __device__ __forceinline__ uint32_t swz128(uint32_t off) {
    return off ^ ((off >> 3) & 0x70u);
}

// ---------------- SMEM layout (bytes) ----------------
#define SM_AHI   0          // 16384 (SW128 swizzled)
#define SM_ALO   16384      // 16384
#define SM_B     32768      // 2 stages x 16384 (each: HI 8192, LO 8192)
#define SM_EE    65536      // 2 x 256  (staged -e/2 values)
#define SM_BIDX  66048      // 512
#define SM_RED   66560      // 1024
#define SM_UC    67584      // 16
#define SM_UL    67600      // 512
#define SM_TOTAL 68112

// ---------------- setup: coalesced, 16 blocks x 256 thr ----------------
__global__ void vq_setup(const float* __restrict__ E, int K) {
    __shared__ float Et[64][65];
    int k0 = blockIdx.x * 64;
    int t = threadIdx.x;
    int kl = t & 63;
    int dq = t >> 6;
#pragma unroll
    for (int i = 0; i < 16; i++) {
        int d = dq + i * 4;
        Et[kl][d] = E[d * K + k0 + kl];     // coalesced: consecutive kl
    }
    __syncthreads();
    if (t < 64) {
        float s = 0.f;
#pragma unroll
        for (int d = 0; d < DD; d++) {
            float v = Et[t][d];
            s = __fadd_rn(s, __fmul_rn(v, v));   // sequential, no fma (ref order)
        }
        g_enorm[k0 + t] = s;
        g_eneg2[k0 + t] = -0.5f * s;
        g_hist[k0 + t] = 0;
    }
#pragma unroll
    for (int i = 0; i < 16; i++) {
        int k = k0 + dq + i * 4;
        float v = Et[dq + i * 4][kl];
        g_ET[k * DD + kl] = v;               // coalesced per code row
        __nv_bfloat16 h = __float2bfloat16(v);
        g_Bhi[k * DD + kl] = h;
        g_Blo[k * DD + kl] = __float2bfloat16(v - __bfloat162float(h));
    }
}

// exact reference-rounding distance (same chain that passed R2)
static __device__ __forceinline__ float exact_dist(const float* __restrict__ xr,
                                                   int k, float xxv) {
    float s = 0.f;
    const float4* ep = (const float4*)(g_ET + k * DD);
#pragma unroll
    for (int d4 = 0; d4 < DD / 4; d4++) {
        float4 e = ep[d4];
        float4 x = ((const float4*)xr)[d4];
        s = __fmaf_rn(x.x, e.x, s);
        s = __fmaf_rn(x.y, e.y, s);
        s = __fmaf_rn(x.z, e.z, s);
        s = __fmaf_rn(x.w, e.w, s);
    }
    return __fadd_rn(__fsub_rn(xxv, __fmul_rn(2.0f, s)), g_enorm[k]);
}

__global__ __launch_bounds__(NTHREADS, 3)
void vq_main(const float* __restrict__ X, float* __restrict__ out,
             int rows, int row0, int poff)
{
    extern __shared__ char smem[];
    uint32_t sb = smem_to_u32(smem);
    int*  bIdx = (int*)(smem + SM_BIDX);
    float* red = (float*)(smem + SM_RED);
    int*  ucP  = (int*)(smem + SM_UC);
    int*  ulist= (int*)(smem + SM_UL);

    int tid = threadIdx.x;
    int lane = tid & 31;
    int wid = tid >> 5;
    int r0blk = row0 + blockIdx.x * TM;

    if (tid == 0) *ucP = 0;

    // ---- A conversion: X (global, coalesced f4) -> bf16 hi/lo swizzled smem ----
    {
        const float4* Xg4 = (const float4*)X;
        int maxq = rows * (DD / 4) - 1;
#pragma unroll
        for (int i = 0; i < (TM * DD / 4) / NTHREADS; i++) {
            int idx = tid + i * NTHREADS;
            int g = r0blk * (DD / 4) + idx;
            float4 v = Xg4[g <= maxq ? g : maxq];
            __nv_bfloat162 h0, h1, l0, l1;
            h0.x = __float2bfloat16(v.x); h0.y = __float2bfloat16(v.y);
            h1.x = __float2bfloat16(v.z); h1.y = __float2bfloat16(v.w);
            l0.x = __float2bfloat16(v.x - __bfloat162float(h0.x));
            l0.y = __float2bfloat16(v.y - __bfloat162float(h0.y));
            l1.x = __float2bfloat16(v.z - __bfloat162float(h1.x));
            l1.y = __float2bfloat16(v.w - __bfloat162float(h1.y));
            int row = idx >> 4;
            int dpos = (idx & 15) * 4;
            uint32_t off = (uint32_t)row * 128 + (uint32_t)dpos * 2;
            uint32_t swo = swz128(off);
            uint2 hp; hp.x = *(uint32_t*)&h0; hp.y = *(uint32_t*)&h1;
            uint2 lp; lp.x = *(uint32_t*)&l0; lp.y = *(uint32_t*)&l1;
            *(uint2*)(smem + SM_AHI + swo) = hp;
            *(uint2*)(smem + SM_ALO + swo) = lp;
        }
    }

    // ---- stage B tile 0 (cp.async): 512 16B chunks + eneg2 ----
    {
        const float4* shi = (const float4*)(g_Bhi);
        const float4* slo = (const float4*)(g_Blo);
#pragma unroll
        for (int i = 0; i < 2; i++) {
            int idx = tid + i * NTHREADS;
            uint32_t sw = swz128((uint32_t)idx * 16);
            cpa16(sb + SM_B + sw, shi + idx);
            cpa16(sb + SM_B + 8192 + sw, slo + idx);
        }
        if (tid < NTILE) cpa4(sb + SM_EE + (uint32_t)tid * 4, g_eneg2 + tid);
        cpa_commit();
    }
    __syncthreads();   // A smem ready

    // ---- A fragments (loop-invariant): warp strip rows [wid*16, +16) ----
    int wstrip = wid * 16;
    uint32_t ahi[4][4], alo[4][4];
    {
        int m = wstrip + (lane & 15);
        uint32_t kbh = (uint32_t)(lane >> 4) * 16;
#pragma unroll
        for (int ks = 0; ks < 4; ks++) {
            uint32_t off = (uint32_t)m * 128 + (uint32_t)ks * 32 + kbh;
            ldsm4(ahi[ks][0], ahi[ks][1], ahi[ks][2], ahi[ks][3],
                  sb + SM_AHI + swz128(off));
            ldsm4(alo[ks][0], alo[ks][1], alo[ks][2], alo[ks][3],
                  sb + SM_ALO + swz128(off));
        }
    }

    int rlo = wstrip + (lane >> 2);
    int rhi = rlo + 8;

    // scalar top-2 state per row; screen metric = s - e/2, argMAX
    float m1a = -3.4e38f, m2a = -3.4e38f;
    float m1b = -3.4e38f, m2b = -3.4e38f;
    int i1a = 0, i1b = 0;

    uint32_t bcode = (uint32_t)((lane & 7) + ((lane & 16) ? 8 : 0));
    uint32_t bkb   = (uint32_t)(((lane >> 3) & 1) * 16);
    int cb = 2 * (lane & 3);

    for (int t = 0; t < NKT; t++) {
        int kt = t * NTILE;
        cpa_wait0();
        __syncthreads();            // tile t ready, prior stage free

        if (t + 1 < NKT) {          // stage tile t+1 (overlaps compute)
            const float4* shi = (const float4*)(g_Bhi + (kt + NTILE) * DD);
            const float4* slo = (const float4*)(g_Blo + (kt + NTILE) * DD);
            uint32_t bb = sb + SM_B + (uint32_t)((t + 1) & 1) * 16384;
#pragma unroll
            for (int i = 0; i < 2; i++) {
                int idx = tid + i * NTHREADS;
                uint32_t sw = swz128((uint32_t)idx * 16);
                cpa16(bb + sw, shi + idx);
                cpa16(bb + 8192 + sw, slo + idx);
            }
            if (tid < NTILE)
                cpa4(sb + SM_EE + (uint32_t)((t + 1) & 1) * 256 + (uint32_t)tid * 4,
                     g_eneg2 + kt + NTILE + tid);
            cpa_commit();
        }

        uint32_t bb = sb + SM_B + (uint32_t)(t & 1) * 16384;
        const float* Een = (const float*)(smem + SM_EE + (t & 1) * 256);

        // two n-halves of 32 codes each (keeps acc at 16 regs)
#pragma unroll
        for (int h = 0; h < 2; h++) {
            // acc init = -e/2 (folds the ||e||^2 term into the GEMM)
            float acc[4][4];
#pragma unroll
            for (int nt = 0; nt < 4; nt++) {
                float2 ep = *(const float2*)(Een + h * 32 + nt * 8 + cb);
                acc[nt][0] = ep.x; acc[nt][1] = ep.y;
                acc[nt][2] = ep.x; acc[nt][3] = ep.y;
            }
#pragma unroll
            for (int np = 0; np < 2; np++) {
                uint32_t n0 = (uint32_t)(h * 2 + np) * 16;
#pragma unroll
                for (int ks = 0; ks < 4; ks++) {
                    uint32_t off = swz128((n0 + bcode) * 128 + (uint32_t)ks * 32 + bkb);
                    uint32_t bh0, bh1, bh2, bh3, bl0, bl1, bl2, bl3;
                    ldsm4(bh0, bh1, bh2, bh3, bb + off);
                    ldsm4(bl0, bl1, bl2, bl3, bb + 8192 + off);
                    mma_bf16(acc[2 * np],     ahi[ks], bh0, bh1);
                    mma_bf16(acc[2 * np],     ahi[ks], bl0, bl1);
                    mma_bf16(acc[2 * np],     alo[ks], bh0, bh1);
                    mma_bf16(acc[2 * np + 1], ahi[ks], bh2, bh3);
                    mma_bf16(acc[2 * np + 1], ahi[ks], bl2, bl3);
                    mma_bf16(acc[2 * np + 1], alo[ks], bh2, bh3);
                }
            }
            // acc[nt][j] = (s - e/2) at col h*32+nt*8+cb+(j&1), row (j<2 ? rlo : rhi)
            // scalar top-2 tracking: 3 FMNMX/value, index-free
            float holdA = m1a, holdB = m1b;
#pragma unroll
            for (int nt = 0; nt < 4; nt++) {
                m2a = fmaxf(m2a, fminf(m1a, acc[nt][0]));
                m1a = fmaxf(m1a, acc[nt][0]);
                m2a = fmaxf(m2a, fminf(m1a, acc[nt][1]));
                m1a = fmaxf(m1a, acc[nt][1]);
                m2b = fmaxf(m2b, fminf(m1b, acc[nt][2]));
                m1b = fmaxf(m1b, acc[nt][2]);
                m2b = fmaxf(m2b, fminf(m1b, acc[nt][3]));
                m1b = fmaxf(m1b, acc[nt][3]);
            }
            // rare: max improved this half-tile -> recover first matching index
            int cbase = kt + h * 32 + cb;
            if (m1a != holdA) {
                int f = i1a; bool fd = false;
#pragma unroll
                for (int nt = 0; nt < 4; nt++) {
                    if (!fd && acc[nt][0] == m1a) { f = cbase + nt * 8;     fd = true; }
                    if (!fd && acc[nt][1] == m1a) { f = cbase + nt * 8 + 1; fd = true; }
                }
                i1a = f;
            }
            if (m1b != holdB) {
                int f = i1b; bool fd = false;
#pragma unroll
                for (int nt = 0; nt < 4; nt++) {
                    if (!fd && acc[nt][2] == m1b) { f = cbase + nt * 8;     fd = true; }
                    if (!fd && acc[nt][3] == m1b) { f = cbase + nt * 8 + 1; fd = true; }
                }
                i1b = f;
            }
        }
    }

    // ---- quad reduce (argmax, m2); flag ambiguous rows ----
#pragma unroll
    for (int s = 0; s < 2; s++) {
        float m1 = (s == 0) ? m1a : m1b;
        float m2 = (s == 0) ? m2a : m2b;
        int   i1 = (s == 0) ? i1a : i1b;
        int   rr = (s == 0) ? rlo : rhi;
#pragma unroll
        for (int m = 1; m < 4; m <<= 1) {
            float om1 = __shfl_xor_sync(0xffffffffu, m1, m);
            int   oi1 = __shfl_xor_sync(0xffffffffu, i1, m);
            float om2 = __shfl_xor_sync(0xffffffffu, m2, m);
            float lo2 = fminf(m1, om1);
            m2 = fmaxf(fmaxf(m2, om2), lo2);
            if (om1 > m1 || (om1 == m1 && oi1 < i1)) { m1 = om1; i1 = oi1; }
        }
        if ((lane & 3) == 0) {
            bIdx[rr] = i1;
            if (m1 - m2 < THRESH_MAX) {          // ambiguous -> exact rescan
                int u = atomicAdd(ucP, 1);
                ulist[u] = rr;
            }
        }
    }
    __syncthreads();

    // ---- exact full scan for flagged rows (reference chain, warp per row) ----
    {
        int nu = *ucP;
        for (int u = wid; u < nu; u += 8) {
            int rr = ulist[u];
            const float* xr = X + (size_t)(r0blk + rr) * DD;
            float xxv = 0.f;
#pragma unroll
            for (int d = 0; d < DD; d++)
                xxv = __fadd_rn(xxv, __fmul_rn(xr[d], xr[d]));   // ref order
            float bd = 3.4e38f;
            int bk = 0;
            int cbase = lane * 32;
            for (int c = cbase; c < cbase + 32; c++) {
                float d = exact_dist(xr, c, xxv);
                if (d < bd) { bd = d; bk = c; }   // ascending k: first-index ties
            }
#pragma unroll
            for (int m = 1; m < 32; m <<= 1) {
                float od = __shfl_xor_sync(0xffffffffu, bd, m);
                int   ok = __shfl_xor_sync(0xffffffffu, bk, m);
                if (od < bd || (od == bd && ok < bk)) { bd = od; bk = ok; }
            }
            if (lane == 0) bIdx[rr] = bk;
        }
    }
    __syncthreads();

    // ---- histogram (int atomics, deterministic) ----
    if (tid < TM && (r0blk + tid) < rows) atomicAdd(&g_hist[bIdx[tid]], 1);

    // ---- gather codebook rows, STE rounding, q write, SSE partial (f4) ----
    float sse = 0.f;
    {
        const float4* Xg4 = (const float4*)X;
        float4* Og4 = (float4*)out;
#pragma unroll
        for (int i = 0; i < (TM * DD / 4) / NTHREADS; i++) {
            int idx = tid + i * NTHREADS;
            int row = idx >> 4;
            int d4 = idx & 15;
            if (r0blk + row < rows) {
                float4 q = ((const float4*)(g_ET + bIdx[row] * DD))[d4];
                float4 x = Xg4[r0blk * (DD / 4) + idx];
                float4 df, o;
                df.x = __fsub_rn(q.x, x.x); o.x = __fadd_rn(x.x, df.x);
                df.y = __fsub_rn(q.y, x.y); o.y = __fadd_rn(x.y, df.y);
                df.z = __fsub_rn(q.z, x.z); o.z = __fadd_rn(x.z, df.z);
                df.w = __fsub_rn(q.w, x.w); o.w = __fadd_rn(x.w, df.w);
                Og4[r0blk * (DD / 4) + idx] = o;
                sse += df.x * df.x + df.y * df.y + df.z * df.z + df.w * df.w;
            }
        }
    }
    red[tid] = sse;
    __syncthreads();
    for (int off = NTHREADS / 2; off > 0; off >>= 1) {
        if (tid < off) red[tid] += red[tid + off];
        __syncthreads();
    }
    if (tid == 0) g_partial[poff + blockIdx.x] = red[0];
}

__global__ void vq_finalize(float* __restrict__ out, int nblocks, int rows, int K, long long outsz) {
    __shared__ float sh[1024];
    int tid = threadIdx.x;

    float s = 0.f;
    for (int i = tid; i < nblocks; i += blockDim.x) s += g_partial[i];
    sh[tid] = s;
    __syncthreads();
    for (int off = 512; off > 0; off >>= 1) {
        if (tid < off) sh[tid] += sh[tid + off];
        __syncthreads();
    }
    float sse = sh[0];
    __syncthreads();

    float invN = 1.0f / (float)rows;
    float ent = 0.f;
    for (int k = tid; k < K; k += blockDim.x) {
        float p = (float)g_hist[k] * invN;
        ent += p * logf(p + 1e-10f);
    }
    sh[tid] = ent;
    __syncthreads();
    for (int off = 512; off > 0; off >>= 1) {
        if (tid < off) sh[tid] += sh[tid + off];
        __syncthreads();
    }

    if (tid == 0) {
        long long nd = (long long)rows * DD;
        if (outsz > nd)     out[nd]     = 2.f * sse / (float)nd;
        if (outsz > nd + 1) out[nd + 1] = expf(-sh[0]);
    }
}

extern "C" void kernel_launch(void* const* d_in, const int* in_sizes, int n_in,
                              void* d_out, int out_size) {
    const float* X = (const float*)d_in[0];
    const float* E = (const float*)d_in[1];
    float* out = (float*)d_out;

    int nd = in_sizes[0];
    int rows = nd / DD;              // 131072
    int K = in_sizes[1] / DD;        // 1024

    int grid = (rows + TM - 1) / TM; // 1024
    // wave-balanced split: 888 = 2 full waves at 3 CTAs/SM x 148 SMs; 136 = tail
    int c0 = 888;
    if (c0 > grid) c0 = grid;
    int c1 = grid - c0;

    cudaFuncSetAttribute(vq_main, cudaFuncAttributeMaxDynamicSharedMemorySize, SM_TOTAL);

    vq_setup<<<K / 64, 256>>>(E, K);
    vq_main<<<c0, NTHREADS, SM_TOTAL>>>(X, out, rows, 0, 0);
    if (c1 > 0)
        vq_main<<<c1, NTHREADS, SM_TOTAL>>>(X, out, rows, c0 * TM, c0);
    vq_finalize<<<1, 1024>>>(out, grid, rows, K, (long long)out_size);
}

// round 16
// speedup vs baseline: 1.0569x; 1.0569x over previous
#include <cuda_runtime.h>
#include <cuda_bf16.h>
#include <cstdint>
#include <math.h>

#define DD 64
#define KTOT 1024
#define TM 128
#define NTHREADS 256
#define NTILE 64
#define NKT (KTOT / NTILE)
#define THRESH_MAX 5e-4f   // gap threshold in (s - e/2) domain == 1e-3 in dist domain

// ---------------- scratch (no allocations allowed) ----------------
__device__ float          g_enorm[KTOT];
__device__ float          g_eneg2[KTOT];        // -0.5 * ||e||^2 (acc init)
__device__ float          g_ET[KTOT * DD];      // codebook rows, k-major, f32
__device__ __nv_bfloat16  g_Bhi[KTOT * DD];     // bf16 hi split, [code][d]
__device__ __nv_bfloat16  g_Blo[KTOT * DD];     // bf16 lo split, [code][d]
__device__ int            g_hist[KTOT];
__device__ float          g_partial[2048];

// ---------------- PTX helpers (baseline PTX only) ----------------
static __device__ __forceinline__ uint32_t smem_to_u32(const void* p) {
    uint32_t a;
    asm("{ .reg .u64 t; cvta.to.shared.u64 t, %1; cvt.u32.u64 %0, t; }" : "=r"(a) : "l"(p));
    return a;
}
static __device__ __forceinline__ void ldsm4(uint32_t& r0, uint32_t& r1,
    uint32_t& r2, uint32_t& r3, uint32_t addr) {
    asm volatile("ldmatrix.sync.aligned.m8n8.x4.shared.b16 {%0,%1,%2,%3}, [%4];"
        : "=r"(r0), "=r"(r1), "=r"(r2), "=r"(r3) : "r"(addr));
}
static __device__ __forceinline__ void mma_bf16(float* c, const uint32_t* a,
    uint32_t b0, uint32_t b1) {
    asm volatile(
        "mma.sync.aligned.m16n8k16.row.col.f32.bf16.bf16.f32 "
        "{%0,%1,%2,%3}, {%4,%5,%6,%7}, {%8,%9}, {%0,%1,%2,%3};"
        : "+f"(c[0]), "+f"(c[1]), "+f"(c[2]), "+f"(c[3])
        : "r"(a[0]), "r"(a[1]), "r"(a[2]), "r"(a[3]), "r"(b0), "r"(b1));
}
static __device__ __forceinline__ void cpa16(uint32_t dst, const void* src) {
    asm volatile("cp.async.ca.shared.global [%0], [%1], 16;" :: "r"(dst), "l"(src));
}
static __device__ __forceinline__ void cpa4(uint32_t dst, const void* src) {
    asm volatile("cp.async.ca.shared.global [%0], [%1], 4;" :: "r"(dst), "l"(src));
}
static __device__ __forceinline__ void cpa_commit() {
    asm volatile("cp.async.commit_group;" ::: "memory");
}
static __device__ __forceinline__ void cpa_wait0() {
    asm volatile("cp.async.wait_group 0;" ::: "memory");
}
static __device__ __forceinline__ uint32_t swz128(uint32_t off) {
    return off ^ ((off >> 3) & 0x70u);
}

// ---------------- SMEM layout (bytes) ----------------
#define SM_AHI   0          // 16384 (SW128 swizzled)
#define SM_ALO   16384      // 16384
#define SM_B     32768      // 2 stages x 16384 (each: HI 8192, LO 8192)
#define SM_EE    65536      // 2 x 256  (staged -e/2 values)
#define SM_BIDX  66048      // 512
#define SM_RED   66560      // 1024
#define SM_UC    67584      // 16
#define SM_UL    67600      // 512
#define SM_TOTAL 68112

// ---------------- setup: coalesced, 16 blocks x 256 thr ----------------
__global__ void vq_setup(const float* __restrict__ E, int K) {
    __shared__ float Et[64][65];
    int k0 = blockIdx.x * 64;
    int t = threadIdx.x;
    int kl = t & 63;
    int dq = t >> 6;
#pragma unroll
    for (int i = 0; i < 16; i++) {
        int d = dq + i * 4;
        Et[kl][d] = E[d * K + k0 + kl];     // coalesced: consecutive kl
    }
    __syncthreads();
    if (t < 64) {
        float s = 0.f;
#pragma unroll
        for (int d = 0; d < DD; d++) {
            float v = Et[t][d];
            s = __fadd_rn(s, __fmul_rn(v, v));   // sequential, no fma (ref order)
        }
        g_enorm[k0 + t] = s;
        g_eneg2[k0 + t] = -0.5f * s;
        g_hist[k0 + t] = 0;
    }
#pragma unroll
    for (int i = 0; i < 16; i++) {
        int k = k0 + dq + i * 4;
        float v = Et[dq + i * 4][kl];
        g_ET[k * DD + kl] = v;               // coalesced per code row
        __nv_bfloat16 h = __float2bfloat16(v);
        g_Bhi[k * DD + kl] = h;
        g_Blo[k * DD + kl] = __float2bfloat16(v - __bfloat162float(h));
    }
}

// exact reference-rounding distance (same chain that passed R2)
static __device__ __forceinline__ float exact_dist(const float* __restrict__ xr,
                                                   int k, float xxv) {
    float s = 0.f;
    const float4* ep = (const float4*)(g_ET + k * DD);
#pragma unroll
    for (int d4 = 0; d4 < DD / 4; d4++) {
        float4 e = ep[d4];
        float4 x = ((const float4*)xr)[d4];
        s = __fmaf_rn(x.x, e.x, s);
        s = __fmaf_rn(x.y, e.y, s);
        s = __fmaf_rn(x.z, e.z, s);
        s = __fmaf_rn(x.w, e.w, s);
    }
    return __fadd_rn(__fsub_rn(xxv, __fmul_rn(2.0f, s)), g_enorm[k]);
}

// branchless top-2 tracker, argMAX domain; equality keeps old index
// (values processed in ascending k -> first-index tie semantics)
static __device__ __forceinline__ void upd2max(float d, int c,
                                               float& m1, int& i1, float& m2) {
    bool gt = d > m1;
    m2 = fmaxf(m2, gt ? m1 : d);
    i1 = gt ? c : i1;
    m1 = gt ? d : m1;
}

__global__ __launch_bounds__(NTHREADS, 3)
void vq_main(const float* __restrict__ X, float* __restrict__ out,
             int rows, int row0, int poff)
{
    extern __shared__ char smem[];
    uint32_t sb = smem_to_u32(smem);
    int*  bIdx = (int*)(smem + SM_BIDX);
    float* red = (float*)(smem + SM_RED);
    int*  ucP  = (int*)(smem + SM_UC);
    int*  ulist= (int*)(smem + SM_UL);

    int tid = threadIdx.x;
    int lane = tid & 31;
    int wid = tid >> 5;
    int r0blk = row0 + blockIdx.x * TM;

    if (tid == 0) *ucP = 0;

    // ---- A conversion: X (global, coalesced f4) -> bf16 hi/lo swizzled smem ----
    {
        const float4* Xg4 = (const float4*)X;
        int maxq = rows * (DD / 4) - 1;
#pragma unroll
        for (int i = 0; i < (TM * DD / 4) / NTHREADS; i++) {
            int idx = tid + i * NTHREADS;
            int g = r0blk * (DD / 4) + idx;
            float4 v = Xg4[g <= maxq ? g : maxq];
            __nv_bfloat162 h0, h1, l0, l1;
            h0.x = __float2bfloat16(v.x); h0.y = __float2bfloat16(v.y);
            h1.x = __float2bfloat16(v.z); h1.y = __float2bfloat16(v.w);
            l0.x = __float2bfloat16(v.x - __bfloat162float(h0.x));
            l0.y = __float2bfloat16(v.y - __bfloat162float(h0.y));
            l1.x = __float2bfloat16(v.z - __bfloat162float(h1.x));
            l1.y = __float2bfloat16(v.w - __bfloat162float(h1.y));
            int row = idx >> 4;
            int dpos = (idx & 15) * 4;
            uint32_t off = (uint32_t)row * 128 + (uint32_t)dpos * 2;
            uint32_t swo = swz128(off);
            uint2 hp; hp.x = *(uint32_t*)&h0; hp.y = *(uint32_t*)&h1;
            uint2 lp; lp.x = *(uint32_t*)&l0; lp.y = *(uint32_t*)&l1;
            *(uint2*)(smem + SM_AHI + swo) = hp;
            *(uint2*)(smem + SM_ALO + swo) = lp;
        }
    }

    // ---- stage B tile 0 (cp.async): 512 16B chunks + eneg2 ----
    {
        const float4* shi = (const float4*)(g_Bhi);
        const float4* slo = (const float4*)(g_Blo);
#pragma unroll
        for (int i = 0; i < 2; i++) {
            int idx = tid + i * NTHREADS;
            uint32_t sw = swz128((uint32_t)idx * 16);
            cpa16(sb + SM_B + sw, shi + idx);
            cpa16(sb + SM_B + 8192 + sw, slo + idx);
        }
        if (tid < NTILE) cpa4(sb + SM_EE + (uint32_t)tid * 4, g_eneg2 + tid);
        cpa_commit();
    }
    __syncthreads();   // A smem ready

    // ---- A fragments (loop-invariant): warp strip rows [wid*16, +16) ----
    int wstrip = wid * 16;
    uint32_t ahi[4][4], alo[4][4];
    {
        int m = wstrip + (lane & 15);
        uint32_t kbh = (uint32_t)(lane >> 4) * 16;
#pragma unroll
        for (int ks = 0; ks < 4; ks++) {
            uint32_t off = (uint32_t)m * 128 + (uint32_t)ks * 32 + kbh;
            ldsm4(ahi[ks][0], ahi[ks][1], ahi[ks][2], ahi[ks][3],
                  sb + SM_AHI + swz128(off));
            ldsm4(alo[ks][0], alo[ks][1], alo[ks][2], alo[ks][3],
                  sb + SM_ALO + swz128(off));
        }
    }

    int rlo = wstrip + (lane >> 2);
    int rhi = rlo + 8;

    // top-2 state per row; screen metric = s - e/2, argMAX
    float m1a = -3.4e38f, m2a = -3.4e38f;
    float m1b = -3.4e38f, m2b = -3.4e38f;
    int i1a = 0, i1b = 0;

    uint32_t bcode = (uint32_t)((lane & 7) + ((lane & 16) ? 8 : 0));
    uint32_t bkb   = (uint32_t)(((lane >> 3) & 1) * 16);
    int cb = 2 * (lane & 3);

    for (int t = 0; t < NKT; t++) {
        int kt = t * NTILE;
        cpa_wait0();
        __syncthreads();            // tile t ready, prior stage free

        if (t + 1 < NKT) {          // stage tile t+1 (overlaps compute)
            const float4* shi = (const float4*)(g_Bhi + (kt + NTILE) * DD);
            const float4* slo = (const float4*)(g_Blo + (kt + NTILE) * DD);
            uint32_t bb = sb + SM_B + (uint32_t)((t + 1) & 1) * 16384;
#pragma unroll
            for (int i = 0; i < 2; i++) {
                int idx = tid + i * NTHREADS;
                uint32_t sw = swz128((uint32_t)idx * 16);
                cpa16(bb + sw, shi + idx);
                cpa16(bb + 8192 + sw, slo + idx);
            }
            if (tid < NTILE)
                cpa4(sb + SM_EE + (uint32_t)((t + 1) & 1) * 256 + (uint32_t)tid * 4,
                     g_eneg2 + kt + NTILE + tid);
            cpa_commit();
        }

        uint32_t bb = sb + SM_B + (uint32_t)(t & 1) * 16384;
        const float* Een = (const float*)(smem + SM_EE + (t & 1) * 256);

        // two n-halves of 32 codes each (keeps acc at 16 regs)
#pragma unroll
        for (int h = 0; h < 2; h++) {
            // acc init = -e/2 (folds the ||e||^2 term into the GEMM)
            float acc[4][4];
#pragma unroll
            for (int nt = 0; nt < 4; nt++) {
                float2 ep = *(const float2*)(Een + h * 32 + nt * 8 + cb);
                acc[nt][0] = ep.x; acc[nt][1] = ep.y;
                acc[nt][2] = ep.x; acc[nt][3] = ep.y;
            }
#pragma unroll
            for (int np = 0; np < 2; np++) {
                uint32_t n0 = (uint32_t)(h * 2 + np) * 16;
#pragma unroll
                for (int ks = 0; ks < 4; ks++) {
                    uint32_t off = swz128((n0 + bcode) * 128 + (uint32_t)ks * 32 + bkb);
                    uint32_t bh0, bh1, bh2, bh3, bl0, bl1, bl2, bl3;
                    ldsm4(bh0, bh1, bh2, bh3, bb + off);
                    ldsm4(bl0, bl1, bl2, bl3, bb + 8192 + off);
                    mma_bf16(acc[2 * np],     ahi[ks], bh0, bh1);
                    mma_bf16(acc[2 * np],     ahi[ks], bl0, bl1);
                    mma_bf16(acc[2 * np],     alo[ks], bh0, bh1);
                    mma_bf16(acc[2 * np + 1], ahi[ks], bh2, bh3);
                    mma_bf16(acc[2 * np + 1], ahi[ks], bl2, bl3);
                    mma_bf16(acc[2 * np + 1], alo[ks], bh2, bh3);
                }
            }
            // acc[nt][j] = (s - e/2) at col h*32+nt*8+cb+(j&1), row (j<2 ? rlo : rhi)
            // branchless top-2 (R13-proven select form, argMAX)
#pragma unroll
            for (int nt = 0; nt < 4; nt++) {
                int c0 = kt + h * 32 + nt * 8 + cb;
                upd2max(acc[nt][0], c0,     m1a, i1a, m2a);
                upd2max(acc[nt][1], c0 + 1, m1a, i1a, m2a);
                upd2max(acc[nt][2], c0,     m1b, i1b, m2b);
                upd2max(acc[nt][3], c0 + 1, m1b, i1b, m2b);
            }
        }
    }

    // ---- quad reduce (argmax, m2); flag ambiguous rows ----
#pragma unroll
    for (int s = 0; s < 2; s++) {
        float m1 = (s == 0) ? m1a : m1b;
        float m2 = (s == 0) ? m2a : m2b;
        int   i1 = (s == 0) ? i1a : i1b;
        int   rr = (s == 0) ? rlo : rhi;
#pragma unroll
        for (int m = 1; m < 4; m <<= 1) {
            float om1 = __shfl_xor_sync(0xffffffffu, m1, m);
            int   oi1 = __shfl_xor_sync(0xffffffffu, i1, m);
            float om2 = __shfl_xor_sync(0xffffffffu, m2, m);
            float lo2 = fminf(m1, om1);
            m2 = fmaxf(fmaxf(m2, om2), lo2);
            if (om1 > m1 || (om1 == m1 && oi1 < i1)) { m1 = om1; i1 = oi1; }
        }
        if ((lane & 3) == 0) {
            bIdx[rr] = i1;
            if (m1 - m2 < THRESH_MAX) {          // ambiguous -> exact rescan
                int u = atomicAdd(ucP, 1);
                ulist[u] = rr;
            }
        }
    }
    __syncthreads();

    // ---- exact full scan for flagged rows (reference chain, warp per row) ----
    {
        int nu = *ucP;
        for (int u = wid; u < nu; u += 8) {
            int rr = ulist[u];
            const float* xr = X + (size_t)(r0blk + rr) * DD;
            float xxv = 0.f;
#pragma unroll
            for (int d = 0; d < DD; d++)
                xxv = __fadd_rn(xxv, __fmul_rn(xr[d], xr[d]));   // ref order
            float bd = 3.4e38f;
            int bk = 0;
            int cbase = lane * 32;
            for (int c = cbase; c < cbase + 32; c++) {
                float d = exact_dist(xr, c, xxv);
                if (d < bd) { bd = d; bk = c; }   // ascending k: first-index ties
            }
#pragma unroll
            for (int m = 1; m < 32; m <<= 1) {
                float od = __shfl_xor_sync(0xffffffffu, bd, m);
                int   ok = __shfl_xor_sync(0xffffffffu, bk, m);
                if (od < bd || (od == bd && ok < bk)) { bd = od; bk = ok; }
            }
            if (lane == 0) bIdx[rr] = bk;
        }
    }
    __syncthreads();

    // ---- histogram (int atomics, deterministic) ----
    if (tid < TM && (r0blk + tid) < rows) atomicAdd(&g_hist[bIdx[tid]], 1);

    // ---- gather codebook rows, STE rounding, q write, SSE partial (f4) ----
    float sse = 0.f;
    {
        const float4* Xg4 = (const float4*)X;
        float4* Og4 = (float4*)out;
#pragma unroll
        for (int i = 0; i < (TM * DD / 4) / NTHREADS; i++) {
            int idx = tid + i * NTHREADS;
            int row = idx >> 4;
            int d4 = idx & 15;
            if (r0blk + row < rows) {
                float4 q = ((const float4*)(g_ET + bIdx[row] * DD))[d4];
                float4 x = Xg4[r0blk * (DD / 4) + idx];
                float4 df, o;
                df.x = __fsub_rn(q.x, x.x); o.x = __fadd_rn(x.x, df.x);
                df.y = __fsub_rn(q.y, x.y); o.y = __fadd_rn(x.y, df.y);
                df.z = __fsub_rn(q.z, x.z); o.z = __fadd_rn(x.z, df.z);
                df.w = __fsub_rn(q.w, x.w); o.w = __fadd_rn(x.w, df.w);
                Og4[r0blk * (DD / 4) + idx] = o;
                sse += df.x * df.x + df.y * df.y + df.z * df.z + df.w * df.w;
            }
        }
    }
    red[tid] = sse;
    __syncthreads();
    for (int off = NTHREADS / 2; off > 0; off >>= 1) {
        if (tid < off) red[tid] += red[tid + off];
        __syncthreads();
    }
    if (tid == 0) g_partial[poff + blockIdx.x] = red[0];
}

__global__ void vq_finalize(float* __restrict__ out, int nblocks, int rows, int K, long long outsz) {
    __shared__ float sh[1024];
    int tid = threadIdx.x;

    float s = 0.f;
    for (int i = tid; i < nblocks; i += blockDim.x) s += g_partial[i];
    sh[tid] = s;
    __syncthreads();
    for (int off = 512; off > 0; off >>= 1) {
        if (tid < off) sh[tid] += sh[tid + off];
        __syncthreads();
    }
    float sse = sh[0];
    __syncthreads();

    float invN = 1.0f / (float)rows;
    float ent = 0.f;
    for (int k = tid; k < K; k += blockDim.x) {
        float p = (float)g_hist[k] * invN;
        ent += p * logf(p + 1e-10f);
    }
    sh[tid] = ent;
    __syncthreads();
    for (int off = 512; off > 0; off >>= 1) {
        if (tid < off) sh[tid] += sh[tid + off];
        __syncthreads();
    }

    if (tid == 0) {
        long long nd = (long long)rows * DD;
        if (outsz > nd)     out[nd]     = 2.f * sse / (float)nd;
        if (outsz > nd + 1) out[nd + 1] = expf(-sh[0]);
    }
}

extern "C" void kernel_launch(void* const* d_in, const int* in_sizes, int n_in,
                              void* d_out, int out_size) {
    const float* X = (const float*)d_in[0];
    const float* E = (const float*)d_in[1];
    float* out = (float*)d_out;

    int nd = in_sizes[0];
    int rows = nd / DD;              // 131072
    int K = in_sizes[1] / DD;        // 1024

    int grid = (rows + TM - 1) / TM; // 1024
    // wave-balanced split: 888 = 2 full waves at 3 CTAs/SM x 148 SMs; 136 = tail
    int c0 = 888;
    if (c0 > grid) c0 = grid;
    int c1 = grid - c0;

    cudaFuncSetAttribute(vq_main, cudaFuncAttributeMaxDynamicSharedMemorySize, SM_TOTAL);

    vq_setup<<<K / 64, 256>>>(E, K);
    vq_main<<<c0, NTHREADS, SM_TOTAL>>>(X, out, rows, 0, 0);
    if (c1 > 0)
        vq_main<<<c1, NTHREADS, SM_TOTAL>>>(X, out, rows, c0 * TM, c0);
    vq_finalize<<<1, 1024>>>(out, grid, rows, K, (long long)out_size);
}

// round 17
// speedup vs baseline: 1.3487x; 1.2762x over previous
#include <cuda_runtime.h>
#include <cuda_bf16.h>
#include <cstdint>
#include <math.h>

#define DD 64
#define KTOT 1024
#define TM 128
#define NTHREADS 256
#define NTILE 64
#define NKT (KTOT / NTILE)
#define THRESH 1e-3f

// ---------------- scratch (no allocations allowed) ----------------
__device__ float          g_enorm[KTOT];
__device__ float          g_ET[KTOT * DD];      // codebook rows, k-major, f32
__device__ __nv_bfloat16  g_Bhi[KTOT * DD];     // bf16 hi split, [code][d]
__device__ __nv_bfloat16  g_Blo[KTOT * DD];     // bf16 lo split, [code][d]
__device__ int            g_hist[KTOT];
__device__ float          g_partial[2048];

// ---------------- PTX helpers (baseline PTX only) ----------------
static __device__ __forceinline__ uint32_t smem_to_u32(const void* p) {
    uint32_t a;
    asm("{ .reg .u64 t; cvta.to.shared.u64 t, %1; cvt.u32.u64 %0, t; }" : "=r"(a) : "l"(p));
    return a;
}
static __device__ __forceinline__ void ldsm4(uint32_t& r0, uint32_t& r1,
    uint32_t& r2, uint32_t& r3, uint32_t addr) {
    asm volatile("ldmatrix.sync.aligned.m8n8.x4.shared.b16 {%0,%1,%2,%3}, [%4];"
        : "=r"(r0), "=r"(r1), "=r"(r2), "=r"(r3) : "r"(addr));
}
static __device__ __forceinline__ void mma_bf16(float* c, const uint32_t* a,
    uint32_t b0, uint32_t b1) {
    asm volatile(
        "mma.sync.aligned.m16n8k16.row.col.f32.bf16.bf16.f32 "
        "{%0,%1,%2,%3}, {%4,%5,%6,%7}, {%8,%9}, {%0,%1,%2,%3};"
        : "+f"(c[0]), "+f"(c[1]), "+f"(c[2]), "+f"(c[3])
        : "r"(a[0]), "r"(a[1]), "r"(a[2]), "r"(a[3]), "r"(b0), "r"(b1));
}
static __device__ __forceinline__ void cpa16(uint32_t dst, const void* src) {
    asm volatile("cp.async.ca.shared.global [%0], [%1], 16;" :: "r"(dst), "l"(src));
}
static __device__ __forceinline__ void cpa4(uint32_t dst, const void* src) {
    asm volatile("cp.async.ca.shared.global [%0], [%1], 4;" :: "r"(dst), "l"(src));
}
static __device__ __forceinline__ void cpa_commit() {
    asm volatile("cp.async.commit_group;" ::: "memory");
}
static __device__ __forceinline__ void cpa_wait0() {
    asm volatile("cp.async.wait_group 0;" ::: "memory");
}
static __device__ __forceinline__ uint32_t swz128(uint32_t off) {
    return off ^ ((off >> 3) & 0x70u);
}

// ---------------- SMEM layout (bytes) ----------------
#define SM_AHI   0          // 16384 (SW128 swizzled)
#define SM_ALO   16384      // 16384
#define SM_B     32768      // 2 stages x 16384 (each: HI 8192, LO 8192)
#define SM_EE    65536      // 2 x 256
#define SM_BIDX  66048      // 512
#define SM_RED   66560      // 1024
#define SM_UC    67584      // 16
#define SM_UL    67600      // 512
#define SM_TOTAL 68112

// ---------------- setup: coalesced, 16 blocks x 256 thr ----------------
__global__ void vq_setup(const float* __restrict__ E, int K) {
    __shared__ float Et[64][65];
    int k0 = blockIdx.x * 64;
    int t = threadIdx.x;
    int kl = t & 63;
    int dq = t >> 6;
#pragma unroll
    for (int i = 0; i < 16; i++) {
        int d = dq + i * 4;
        Et[kl][d] = E[d * K + k0 + kl];     // coalesced: consecutive kl
    }
    __syncthreads();
    if (t < 64) {
        float s = 0.f;
#pragma unroll
        for (int d = 0; d < DD; d++) {
            float v = Et[t][d];
            s = __fadd_rn(s, __fmul_rn(v, v));   // sequential, no fma (ref order)
        }
        g_enorm[k0 + t] = s;
        g_hist[k0 + t] = 0;
    }
#pragma unroll
    for (int i = 0; i < 16; i++) {
        int k = k0 + dq + i * 4;
        float v = Et[dq + i * 4][kl];
        g_ET[k * DD + kl] = v;               // coalesced per code row
        __nv_bfloat16 h = __float2bfloat16(v);
        g_Bhi[k * DD + kl] = h;
        g_Blo[k * DD + kl] = __float2bfloat16(v - __bfloat162float(h));
    }
}

// exact reference-rounding distance (same chain that passed R2)
static __device__ __forceinline__ float exact_dist(const float* __restrict__ xr,
                                                   int k, float xxv) {
    float s = 0.f;
    const float4* ep = (const float4*)(g_ET + k * DD);
#pragma unroll
    for (int d4 = 0; d4 < DD / 4; d4++) {
        float4 e = ep[d4];
        float4 x = ((const float4*)xr)[d4];
        s = __fmaf_rn(x.x, e.x, s);
        s = __fmaf_rn(x.y, e.y, s);
        s = __fmaf_rn(x.z, e.z, s);
        s = __fmaf_rn(x.w, e.w, s);
    }
    return __fadd_rn(__fsub_rn(xxv, __fmul_rn(2.0f, s)), g_enorm[k]);
}

// branchless top-2 tracker (R13-proven select form, argMIN)
static __device__ __forceinline__ void upd2(float d, int c,
                                            float& m1, int& i1, float& m2) {
    bool lt = d < m1;
    m2 = fminf(m2, lt ? m1 : d);
    i1 = lt ? c : i1;
    m1 = lt ? d : m1;
}

__global__ __launch_bounds__(NTHREADS, 3)
void vq_main(const float* __restrict__ X, float* __restrict__ out,
             int rows, int row0, int poff)
{
    extern __shared__ char smem[];
    uint32_t sb = smem_to_u32(smem);
    int*  bIdx = (int*)(smem + SM_BIDX);
    float* red = (float*)(smem + SM_RED);
    int*  ucP  = (int*)(smem + SM_UC);
    int*  ulist= (int*)(smem + SM_UL);

    int tid = threadIdx.x;
    int lane = tid & 31;
    int wid = tid >> 5;
    int r0blk = row0 + blockIdx.x * TM;

    if (tid == 0) *ucP = 0;

    // ---- A conversion: X (global, coalesced f4) -> bf16 hi/lo swizzled smem ----
    {
        const float4* Xg4 = (const float4*)X;
        int maxq = rows * (DD / 4) - 1;
#pragma unroll
        for (int i = 0; i < (TM * DD / 4) / NTHREADS; i++) {
            int idx = tid + i * NTHREADS;
            int g = r0blk * (DD / 4) + idx;
            float4 v = Xg4[g <= maxq ? g : maxq];
            __nv_bfloat162 h0, h1, l0, l1;
            h0.x = __float2bfloat16(v.x); h0.y = __float2bfloat16(v.y);
            h1.x = __float2bfloat16(v.z); h1.y = __float2bfloat16(v.w);
            l0.x = __float2bfloat16(v.x - __bfloat162float(h0.x));
            l0.y = __float2bfloat16(v.y - __bfloat162float(h0.y));
            l1.x = __float2bfloat16(v.z - __bfloat162float(h1.x));
            l1.y = __float2bfloat16(v.w - __bfloat162float(h1.y));
            int row = idx >> 4;
            int dpos = (idx & 15) * 4;
            uint32_t off = (uint32_t)row * 128 + (uint32_t)dpos * 2;
            uint32_t swo = swz128(off);
            uint2 hp; hp.x = *(uint32_t*)&h0; hp.y = *(uint32_t*)&h1;
            uint2 lp; lp.x = *(uint32_t*)&l0; lp.y = *(uint32_t*)&l1;
            *(uint2*)(smem + SM_AHI + swo) = hp;
            *(uint2*)(smem + SM_ALO + swo) = lp;
        }
    }

    // ---- stage B tile 0 (cp.async): 512 16B chunks ----
    {
        const float4* shi = (const float4*)(g_Bhi);
        const float4* slo = (const float4*)(g_Blo);
#pragma unroll
        for (int i = 0; i < 2; i++) {
            int idx = tid + i * NTHREADS;
            uint32_t sw = swz128((uint32_t)idx * 16);
            cpa16(sb + SM_B + sw, shi + idx);
            cpa16(sb + SM_B + 8192 + sw, slo + idx);
        }
        if (tid < NTILE) cpa4(sb + SM_EE + (uint32_t)tid * 4, g_enorm + tid);
        cpa_commit();
    }
    __syncthreads();   // A smem ready

    // ---- A fragments (loop-invariant): warp strip rows [wid*16, +16) ----
    int wstrip = wid * 16;
    uint32_t ahi[4][4], alo[4][4];
    {
        int m = wstrip + (lane & 15);
        uint32_t kbh = (uint32_t)(lane >> 4) * 16;
#pragma unroll
        for (int ks = 0; ks < 4; ks++) {
            uint32_t off = (uint32_t)m * 128 + (uint32_t)ks * 32 + kbh;
            ldsm4(ahi[ks][0], ahi[ks][1], ahi[ks][2], ahi[ks][3],
                  sb + SM_AHI + swz128(off));
            ldsm4(alo[ks][0], alo[ks][1], alo[ks][2], alo[ks][3],
                  sb + SM_ALO + swz128(off));
        }
    }

    int rlo = wstrip + (lane >> 2);
    int rhi = rlo + 8;

    // top-2 state per row (screened metric: ||e||^2 - 2*s; xx constant dropped)
    float m1a = 3.4e38f, m2a = 3.4e38f;
    float m1b = 3.4e38f, m2b = 3.4e38f;
    int i1a = 0, i1b = 0;

    uint32_t bcode = (uint32_t)((lane & 7) + ((lane & 16) ? 8 : 0));
    uint32_t bkb   = (uint32_t)(((lane >> 3) & 1) * 16);
    int cb = 2 * (lane & 3);

    for (int t = 0; t < NKT; t++) {
        int kt = t * NTILE;
        cpa_wait0();
        __syncthreads();            // tile t ready, prior stage free

        if (t + 1 < NKT) {          // stage tile t+1 (overlaps compute)
            const float4* shi = (const float4*)(g_Bhi + (kt + NTILE) * DD);
            const float4* slo = (const float4*)(g_Blo + (kt + NTILE) * DD);
            uint32_t bb = sb + SM_B + (uint32_t)((t + 1) & 1) * 16384;
#pragma unroll
            for (int i = 0; i < 2; i++) {
                int idx = tid + i * NTHREADS;
                uint32_t sw = swz128((uint32_t)idx * 16);
                cpa16(bb + sw, shi + idx);
                cpa16(bb + 8192 + sw, slo + idx);
            }
            if (tid < NTILE)
                cpa4(sb + SM_EE + (uint32_t)((t + 1) & 1) * 256 + (uint32_t)tid * 4,
                     g_enorm + kt + NTILE + tid);
            cpa_commit();
        }

        uint32_t bb = sb + SM_B + (uint32_t)(t & 1) * 16384;
        const float* Eet = (const float*)(smem + SM_EE + (t & 1) * 256);

        // two n-halves of 32 codes each (keeps acc at 16 regs)
#pragma unroll
        for (int h = 0; h < 2; h++) {
            float acc[4][4];
#pragma unroll
            for (int i = 0; i < 4; i++) {
#pragma unroll
                for (int j = 0; j < 4; j++) acc[i][j] = 0.f;
            }
#pragma unroll
            for (int np = 0; np < 2; np++) {
                uint32_t n0 = (uint32_t)(h * 2 + np) * 16;
#pragma unroll
                for (int ks = 0; ks < 4; ks++) {
                    uint32_t off = swz128((n0 + bcode) * 128 + (uint32_t)ks * 32 + bkb);
                    uint32_t bh0, bh1, bh2, bh3, bl0, bl1, bl2, bl3;
                    ldsm4(bh0, bh1, bh2, bh3, bb + off);
                    ldsm4(bl0, bl1, bl2, bl3, bb + 8192 + off);
                    mma_bf16(acc[2 * np],     ahi[ks], bh0, bh1);
                    mma_bf16(acc[2 * np],     ahi[ks], bl0, bl1);
                    mma_bf16(acc[2 * np],     alo[ks], bh0, bh1);
                    mma_bf16(acc[2 * np + 1], ahi[ks], bh2, bh3);
                    mma_bf16(acc[2 * np + 1], ahi[ks], bl2, bl3);
                    mma_bf16(acc[2 * np + 1], alo[ks], bh2, bh3);
                }
            }
            // epilogue: branchless top-2 on (||e||^2 - 2*s)
#pragma unroll
            for (int nt = 0; nt < 4; nt++) {
                int cl = h * 32 + nt * 8 + cb;
                int c0 = kt + cl;
                float e0 = Eet[cl], e1 = Eet[cl + 1];
                upd2(fmaf(-2.0f, acc[nt][0], e0), c0,     m1a, i1a, m2a);
                upd2(fmaf(-2.0f, acc[nt][1], e1), c0 + 1, m1a, i1a, m2a);
                upd2(fmaf(-2.0f, acc[nt][2], e0), c0,     m1b, i1b, m2b);
                upd2(fmaf(-2.0f, acc[nt][3], e1), c0 + 1, m1b, i1b, m2b);
            }
        }
    }

    // ---- quad reduce (m1, i1, m2); flag ambiguous rows ----
#pragma unroll
    for (int s = 0; s < 2; s++) {
        float m1 = (s == 0) ? m1a : m1b;
        float m2 = (s == 0) ? m2a : m2b;
        int   i1 = (s == 0) ? i1a : i1b;
        int   rr = (s == 0) ? rlo : rhi;
#pragma unroll
        for (int m = 1; m < 4; m <<= 1) {
            float om1 = __shfl_xor_sync(0xffffffffu, m1, m);
            int   oi1 = __shfl_xor_sync(0xffffffffu, i1, m);
            float om2 = __shfl_xor_sync(0xffffffffu, m2, m);
            float hi = fmaxf(m1, om1);
            m2 = fminf(fminf(m2, om2), hi);
            if (om1 < m1 || (om1 == m1 && oi1 < i1)) { m1 = om1; i1 = oi1; }
        }
        if ((lane & 3) == 0) {
            bIdx[rr] = i1;
            if (m2 - m1 < THRESH) {              // ambiguous -> exact rescan
                int u = atomicAdd(ucP, 1);
                ulist[u] = rr;
            }
        }
    }
    __syncthreads();

    // ---- exact full scan for flagged rows (reference chain, warp per row) ----
    {
        int nu = *ucP;
        for (int u = wid; u < nu; u += 8) {
            int rr = ulist[u];
            const float* xr = X + (size_t)(r0blk + rr) * DD;
            float xxv = 0.f;
#pragma unroll
            for (int d = 0; d < DD; d++)
                xxv = __fadd_rn(xxv, __fmul_rn(xr[d], xr[d]));   // ref order
            float bd = 3.4e38f;
            int bk = 0;
            int cbase = lane * 32;
            for (int c = cbase; c < cbase + 32; c++) {
                float d = exact_dist(xr, c, xxv);
                if (d < bd) { bd = d; bk = c; }   // ascending k: first-index ties
            }
#pragma unroll
            for (int m = 1; m < 32; m <<= 1) {
                float od = __shfl_xor_sync(0xffffffffu, bd, m);
                int   ok = __shfl_xor_sync(0xffffffffu, bk, m);
                if (od < bd || (od == bd && ok < bk)) { bd = od; bk = ok; }
            }
            if (lane == 0) bIdx[rr] = bk;
        }
    }
    __syncthreads();

    // ---- histogram (int atomics, deterministic) ----
    if (tid < TM && (r0blk + tid) < rows) atomicAdd(&g_hist[bIdx[tid]], 1);

    // ---- gather codebook rows, STE rounding, q write, SSE partial (f4) ----
    float sse = 0.f;
    {
        const float4* Xg4 = (const float4*)X;
        float4* Og4 = (float4*)out;
#pragma unroll
        for (int i = 0; i < (TM * DD / 4) / NTHREADS; i++) {
            int idx = tid + i * NTHREADS;
            int row = idx >> 4;
            int d4 = idx & 15;
            if (r0blk + row < rows) {
                float4 q = ((const float4*)(g_ET + bIdx[row] * DD))[d4];
                float4 x = Xg4[r0blk * (DD / 4) + idx];
                float4 df, o;
                df.x = __fsub_rn(q.x, x.x); o.x = __fadd_rn(x.x, df.x);
                df.y = __fsub_rn(q.y, x.y); o.y = __fadd_rn(x.y, df.y);
                df.z = __fsub_rn(q.z, x.z); o.z = __fadd_rn(x.z, df.z);
                df.w = __fsub_rn(q.w, x.w); o.w = __fadd_rn(x.w, df.w);
                Og4[r0blk * (DD / 4) + idx] = o;
                sse += df.x * df.x + df.y * df.y + df.z * df.z + df.w * df.w;
            }
        }
    }
    red[tid] = sse;
    __syncthreads();
    for (int off = NTHREADS / 2; off > 0; off >>= 1) {
        if (tid < off) red[tid] += red[tid + off];
        __syncthreads();
    }
    if (tid == 0) g_partial[poff + blockIdx.x] = red[0];
}

__global__ void vq_finalize(float* __restrict__ out, int nblocks, int rows, int K, long long outsz) {
    __shared__ float sh[1024];
    int tid = threadIdx.x;

    float s = 0.f;
    for (int i = tid; i < nblocks; i += blockDim.x) s += g_partial[i];
    sh[tid] = s;
    __syncthreads();
    for (int off = 512; off > 0; off >>= 1) {
        if (tid < off) sh[tid] += sh[tid + off];
        __syncthreads();
    }
    float sse = sh[0];
    __syncthreads();

    float invN = 1.0f / (float)rows;
    float ent = 0.f;
    for (int k = tid; k < K; k += blockDim.x) {
        float p = (float)g_hist[k] * invN;
        ent += p * logf(p + 1e-10f);
    }
    sh[tid] = ent;
    __syncthreads();
    for (int off = 512; off > 0; off >>= 1) {
        if (tid < off) sh[tid] += sh[tid + off];
        __syncthreads();
    }

    if (tid == 0) {
        long long nd = (long long)rows * DD;
        if (outsz > nd)     out[nd]     = 2.f * sse / (float)nd;
        if (outsz > nd + 1) out[nd + 1] = expf(-sh[0]);
    }
}

extern "C" void kernel_launch(void* const* d_in, const int* in_sizes, int n_in,
                              void* d_out, int out_size) {
    const float* X = (const float*)d_in[0];
    const float* E = (const float*)d_in[1];
    float* out = (float*)d_out;

    int nd = in_sizes[0];
    int rows = nd / DD;              // 131072
    int K = in_sizes[1] / DD;        // 1024

    int grid = (rows + TM - 1) / TM; // 1024

    cudaFuncSetAttribute(vq_main, cudaFuncAttributeMaxDynamicSharedMemorySize, SM_TOTAL);

    // single launch: work-stealing fills draining wave slots; no kernel-boundary
    // serialization (the 888+136 split cost a full extra underfilled wave)
    vq_setup<<<K / 64, 256>>>(E, K);
    vq_main<<<grid, NTHREADS, SM_TOTAL>>>(X, out, rows, 0, 0);
    vq_finalize<<<1, 1024>>>(out, grid, rows, K, (long long)out_size);
}